// round 1
// baseline (speedup 1.0000x reference)
#include <cuda_runtime.h>

#define NN 100000
#define NE 800000
#define FIN 128
#define HID 64

static __device__ __constant__ float d_SCALE = 0.70710678118654752440f;
#define BN_EPS 1e-5f

// ---------------- scratch (device globals; no allocation) ----------------
__device__ float g_h0[NN * HID];   // fc output, later reused for h2
__device__ float g_t[NN * HID];    // (h @ w) * norm_out
__device__ float g_agg[NN * HID];  // scatter-add accumulator
__device__ float g_h1[NN * HID];   // conv1 output
__device__ int   g_dego[NN];
__device__ int   g_degi[NN];
__device__ float g_nrmo[NN];       // deg_out^-1/2
__device__ float g_nrmi[NN];       // deg_in^-1/2
__device__ float g_sum[HID];
__device__ float g_ssq[HID];
__device__ float g_bna[HID];
__device__ float g_bnc[HID];

// ---------------- init: zero degrees + BN accumulators ----------------
__global__ void k_zero_small() {
    int i = blockIdx.x * blockDim.x + threadIdx.x;
    if (i < NN) { g_dego[i] = 0; g_degi[i] = 0; }
    if (i < HID) { g_sum[i] = 0.f; g_ssq[i] = 0.f; }
}

__global__ void k_zero_agg() {
    int i = blockIdx.x * blockDim.x + threadIdx.x;
    if (i < NN * (HID / 4)) {
        ((float4*)g_agg)[i] = make_float4(0.f, 0.f, 0.f, 0.f);
    }
}

// ---------------- degree counting ----------------
__global__ void k_degree(const int* __restrict__ src, const int* __restrict__ dst) {
    int e = blockIdx.x * blockDim.x + threadIdx.x;
    if (e < NE) {
        atomicAdd(&g_dego[src[e]], 1);
        atomicAdd(&g_degi[dst[e]], 1);
    }
}

__global__ void k_norms() {
    int i = blockIdx.x * blockDim.x + threadIdx.x;
    if (i < NN) {
        g_nrmo[i] = rsqrtf((float)max(g_dego[i], 1));
        g_nrmi[i] = rsqrtf((float)max(g_degi[i], 1));
    }
}

// ---------------- register-tiled GEMM: C[N,64] = A[N,K] @ W[K,64] ----------------
// MODE 0: A = x (param), C = g_h0, +bias, no norm     (K=128)
// MODE 1: A = g_h0,      C = g_t,  no bias, *nrmo     (K=64)
// MODE 2: A = g_h1,      C = g_t,  no bias, *nrmo     (K=64)
template <int MODE>
__global__ __launch_bounds__(128) void k_gemm(const float* __restrict__ Ain,
                                              const float* __restrict__ W,
                                              const float* __restrict__ bias) {
    constexpr int K = (MODE == 0) ? FIN : HID;
    constexpr int KC = 32;
    const float* A = (MODE == 0) ? Ain : ((MODE == 1) ? (const float*)g_h0 : (const float*)g_h1);
    float* C = (MODE == 0) ? (float*)g_h0 : (float*)g_t;

    __shared__ __align__(16) float At[KC][128];   // transposed A tile
    __shared__ __align__(16) float Ws[KC][HID];

    const int t = threadIdx.x;
    const int r0 = blockIdx.x * 128;
    const int tr = (t >> 3) << 3;   // 0..120 step 8
    const int tc = (t & 7) << 3;    // 0..56  step 8

    float acc[8][8];
#pragma unroll
    for (int i = 0; i < 8; i++)
#pragma unroll
        for (int j = 0; j < 8; j++) acc[i][j] = 0.f;

    const int rload = min(r0 + t, NN - 1);
    const float4* A4 = (const float4*)(A + (long)rload * K);
    const float4* W4 = (const float4*)W;

    for (int k0 = 0; k0 < K; k0 += KC) {
        __syncthreads();
        // load A chunk (each thread owns one row, 8 float4 = 32 k-values), transpose to smem
        float4 v[8];
#pragma unroll
        for (int j = 0; j < 8; j++) v[j] = A4[(k0 >> 2) + j];
#pragma unroll
        for (int j = 0; j < 8; j++) {
            At[4 * j + 0][t] = v[j].x;
            At[4 * j + 1][t] = v[j].y;
            At[4 * j + 2][t] = v[j].z;
            At[4 * j + 3][t] = v[j].w;
        }
        // load W chunk: 32x64 floats = 512 float4, 4 per thread
#pragma unroll
        for (int j = 0; j < 4; j++) {
            int idx = t + j * 128;
            int kk = idx >> 4, c4 = idx & 15;
            *((float4*)&Ws[kk][c4 * 4]) = W4[(k0 + kk) * (HID / 4) + c4];
        }
        __syncthreads();
#pragma unroll
        for (int kk = 0; kk < KC; kk++) {
            float4 a0 = *(const float4*)&At[kk][tr];
            float4 a1 = *(const float4*)&At[kk][tr + 4];
            float4 b0 = *(const float4*)&Ws[kk][tc];
            float4 b1 = *(const float4*)&Ws[kk][tc + 4];
            float aa[8] = {a0.x, a0.y, a0.z, a0.w, a1.x, a1.y, a1.z, a1.w};
            float bb[8] = {b0.x, b0.y, b0.z, b0.w, b1.x, b1.y, b1.z, b1.w};
#pragma unroll
            for (int i = 0; i < 8; i++)
#pragma unroll
                for (int j = 0; j < 8; j++) acc[i][j] += aa[i] * bb[j];
        }
    }

#pragma unroll
    for (int i = 0; i < 8; i++) {
        int r = r0 + tr + i;
        if (r < NN) {
            float sc = (MODE == 0) ? 1.0f : g_nrmo[r];
            float4 o0, o1;
            if (MODE == 0) {
                o0.x = (acc[i][0] + bias[tc + 0]);
                o0.y = (acc[i][1] + bias[tc + 1]);
                o0.z = (acc[i][2] + bias[tc + 2]);
                o0.w = (acc[i][3] + bias[tc + 3]);
                o1.x = (acc[i][4] + bias[tc + 4]);
                o1.y = (acc[i][5] + bias[tc + 5]);
                o1.z = (acc[i][6] + bias[tc + 6]);
                o1.w = (acc[i][7] + bias[tc + 7]);
            } else {
                o0.x = acc[i][0] * sc; o0.y = acc[i][1] * sc;
                o0.z = acc[i][2] * sc; o0.w = acc[i][3] * sc;
                o1.x = acc[i][4] * sc; o1.y = acc[i][5] * sc;
                o1.z = acc[i][6] * sc; o1.w = acc[i][7] * sc;
            }
            *((float4*)&C[(long)r * HID + tc]) = o0;
            *((float4*)&C[(long)r * HID + tc + 4]) = o1;
        }
    }
}

// ---------------- edge scatter: agg[dst] += t[src]  (16 threads / edge, v4 red) ----------------
__global__ void k_scatter(const int* __restrict__ src, const int* __restrict__ dst) {
    int idx = blockIdx.x * blockDim.x + threadIdx.x;
    if (idx >= NE * (HID / 4)) return;
    int e = idx >> 4;
    int c = idx & 15;
    int s = __ldg(&src[e]);
    int d = __ldg(&dst[e]);
    float4 v = ((const float4*)g_t)[s * 16 + c];
    float* p = &g_agg[d * HID + c * 4];
    asm volatile("red.global.add.v4.f32 [%0], {%1,%2,%3,%4};"
                 :: "l"(p), "f"(v.x), "f"(v.y), "f"(v.z), "f"(v.w)
                 : "memory");
}

// ---------------- combine1: h1 = (h0 + agg*nrmi + b1) * SCALE ----------------
__global__ void k_combine1(const float* __restrict__ b1) {
    int idx = blockIdx.x * blockDim.x + threadIdx.x;
    if (idx >= NN * (HID / 4)) return;
    int row = idx >> 4;
    int c4 = idx & 15;
    float4 h = ((const float4*)g_h0)[idx];
    float4 a = ((const float4*)g_agg)[idx];
    float4 b = ((const float4*)b1)[c4];
    float nd = g_nrmi[row];
    float s = d_SCALE;
    float4 r;
    r.x = (h.x + a.x * nd + b.x) * s;
    r.y = (h.y + a.y * nd + b.y) * s;
    r.z = (h.z + a.z * nd + b.z) * s;
    r.w = (h.w + a.w * nd + b.w) * s;
    ((float4*)g_h1)[idx] = r;
}

// ---------------- combine2 + BN partial sums: h2 -> g_h0, accumulate sum/sumsq ----------------
__global__ void k_combine2_bn(const float* __restrict__ b2) {
    const int T = gridDim.x * blockDim.x;  // multiple of 64
    int tg = blockIdx.x * blockDim.x + threadIdx.x;
    int f = tg & 63;
    float bb = b2[f];
    float scl = d_SCALE;
    float s = 0.f, ss = 0.f;
    for (int e = tg; e < NN * HID; e += T) {
        int row = e >> 6;
        float v = (g_h1[e] + g_agg[e] * g_nrmi[row] + bb) * scl;
        g_h0[e] = v;
        s += v;
        ss += v * v;
    }
    __shared__ float sh[256];
    sh[threadIdx.x] = s;
    __syncthreads();
    if (threadIdx.x < 64) {
        float tot = sh[threadIdx.x] + sh[threadIdx.x + 64] + sh[threadIdx.x + 128] + sh[threadIdx.x + 192];
        atomicAdd(&g_sum[threadIdx.x], tot);
    }
    __syncthreads();
    sh[threadIdx.x] = ss;
    __syncthreads();
    if (threadIdx.x < 64) {
        float tot = sh[threadIdx.x] + sh[threadIdx.x + 64] + sh[threadIdx.x + 128] + sh[threadIdx.x + 192];
        atomicAdd(&g_ssq[threadIdx.x], tot);
    }
}

__global__ void k_bn_final(const float* __restrict__ gamma, const float* __restrict__ beta) {
    int f = threadIdx.x;
    float mu = g_sum[f] * (1.0f / NN);
    float var = g_ssq[f] * (1.0f / NN) - mu * mu;
    float a = gamma[f] * rsqrtf(var + BN_EPS);
    g_bna[f] = a;
    g_bnc[f] = beta[f] - mu * a;
}

__global__ void k_out(float* __restrict__ out) {
    int idx = blockIdx.x * blockDim.x + threadIdx.x;
    if (idx >= NN * (HID / 4)) return;
    int c4 = idx & 15;
    float4 h = ((const float4*)g_h0)[idx];
    float4 a = ((const float4*)g_bna)[c4];
    float4 c = ((const float4*)g_bnc)[c4];
    float4 r;
    r.x = h.x * a.x + c.x;
    r.y = h.y * a.y + c.y;
    r.z = h.z * a.z + c.z;
    r.w = h.w * a.w + c.w;
    ((float4*)out)[idx] = r;
}

// ---------------- launch ----------------
extern "C" void kernel_launch(void* const* d_in, const int* in_sizes, int n_in,
                              void* d_out, int out_size) {
    const int* src = (const int*)d_in[0];
    const int* dst = (const int*)d_in[1];
    const float* x = (const float*)d_in[2];
    const float* fc_w = (const float*)d_in[3];
    const float* fc_b = (const float*)d_in[4];
    const float* w1 = (const float*)d_in[5];
    const float* b1 = (const float*)d_in[6];
    const float* w2 = (const float*)d_in[7];
    const float* b2 = (const float*)d_in[8];
    const float* gamma = (const float*)d_in[9];
    const float* beta = (const float*)d_in[10];
    float* out = (float*)d_out;

    const int nb_nodes = (NN + 255) / 256;
    const int nb_vec = (NN * (HID / 4) + 255) / 256;     // 6250
    const int nb_edge = (NE + 255) / 256;
    const int nb_scat = (NE * (HID / 4) + 255) / 256;    // 50000
    const int nb_gemm = (NN + 127) / 128;                // 782

    k_zero_small<<<nb_nodes, 256>>>();
    k_degree<<<nb_edge, 256>>>(src, dst);
    k_norms<<<nb_nodes, 256>>>();

    // h0 = x @ fc_w + fc_b
    k_gemm<0><<<nb_gemm, 128>>>(x, fc_w, fc_b);

    // conv1
    k_gemm<1><<<nb_gemm, 128>>>(nullptr, w1, nullptr);   // t = (h0@w1)*nrmo
    k_zero_agg<<<nb_vec, 256>>>();
    k_scatter<<<nb_scat, 256>>>(src, dst);
    k_combine1<<<nb_vec, 256>>>(b1);                     // h1 = (h0 + agg*nrmi + b1)*S

    // conv2
    k_gemm<2><<<nb_gemm, 128>>>(nullptr, w2, nullptr);   // t = (h1@w2)*nrmo
    k_zero_agg<<<nb_vec, 256>>>();
    k_scatter<<<nb_scat, 256>>>(src, dst);
    k_combine2_bn<<<640, 256>>>(b2);                     // h2 -> g_h0, + BN partials

    k_bn_final<<<1, 64>>>(gamma, beta);
    k_out<<<nb_vec, 256>>>(out);
}

// round 5
// speedup vs baseline: 1.0080x; 1.0080x over previous
#include <cuda_runtime.h>
#include <cstdint>

#define NN 100000
#define NE 800000
#define FIN 128
#define HID 64

static __device__ __constant__ float d_SCALE = 0.70710678118654752440f;
#define BN_EPS 1e-5f

// ---------------- scratch (device globals; no allocation) ----------------
__device__ float g_h0[NN * HID];   // fc output, later reused for h2
__device__ float g_t[NN * HID];    // (h @ w) * norm_out
__device__ float g_agg[NN * HID];  // scatter-add accumulator
__device__ float g_h1[NN * HID];   // conv1 output
__device__ int   g_dego[NN];
__device__ int   g_degi[NN];
__device__ float g_sum[HID];
__device__ float g_ssq[HID];
__device__ float g_bna[HID];
__device__ float g_bnc[HID];

// packed fp32x2 FMA (Blackwell base-family PTX; ptxas won't auto-fuse)
#define FMA2(acc, a, b) \
    asm("fma.rn.f32x2 %0, %1, %2, %0;" : "+l"(acc) : "l"(a), "l"(b))
#define PACK_DUP(dst, fval) \
    asm("mov.b64 %0, {%1, %1};" : "=l"(dst) : "r"(__float_as_uint(fval)))
#define UNPACK2(lo, hi, p) \
    asm("mov.b64 {%0, %1}, %2;" : "=f"(lo), "=f"(hi) : "l"(p))

// ---------------- init: zero degrees + BN accumulators + agg ----------------
__global__ void k_init() {
    int i = blockIdx.x * blockDim.x + threadIdx.x;
    int T = gridDim.x * blockDim.x;
    for (int j = i; j < NN * (HID / 4); j += T)
        ((float4*)g_agg)[j] = make_float4(0.f, 0.f, 0.f, 0.f);
    if (i < NN) { g_dego[i] = 0; g_degi[i] = 0; }
    if (i < HID) { g_sum[i] = 0.f; g_ssq[i] = 0.f; }
}

// ---------------- degree counting ----------------
__global__ void k_degree(const int* __restrict__ src, const int* __restrict__ dst) {
    int e = blockIdx.x * blockDim.x + threadIdx.x;
    if (e < NE) {
        atomicAdd(&g_dego[src[e]], 1);
        atomicAdd(&g_degi[dst[e]], 1);
    }
}

// ======= packed-fp32 register-tiled GEMM: C[N,64] = A[N,K] @ W[K,64] =======
// MODE 0: A = x (param), C = g_h0, +bias              (K=128)
// MODE 1: A = g_h0,      C = g_t,  * dego^-1/2        (K=64)
// MODE 2: A = g_h1,      C = g_t,  * dego^-1/2        (K=64)
template <int MODE>
__global__ __launch_bounds__(128) void k_gemm(const float* __restrict__ Ain,
                                              const float* __restrict__ W,
                                              const float* __restrict__ bias) {
    constexpr int K = (MODE == 0) ? FIN : HID;
    constexpr int KC = 32;

    __shared__ __align__(16) float At[KC][128];   // transposed A tile
    __shared__ __align__(16) float Ws[KC][HID];

    const float* A = (MODE == 0) ? Ain : ((MODE == 1) ? (const float*)g_h0
                                                      : (const float*)g_h1);
    float* C = (MODE == 0) ? (float*)g_h0 : (float*)g_t;

    const int t = threadIdx.x;
    const int r0 = blockIdx.x * 128;
    const int tr = (t >> 3) << 3;   // 0..120 step 8  (8 rows per thread)
    const int tc = (t & 7) << 3;    // 0..56  step 8  (8 cols per thread)

    // acc[i][j] = packed {C[row tr+i][col tc+2j], C[row tr+i][col tc+2j+1]}
    unsigned long long acc[8][4];
#pragma unroll
    for (int i = 0; i < 8; i++)
#pragma unroll
        for (int j = 0; j < 4; j++) acc[i][j] = 0ULL;

    const int rload = min(r0 + t, NN - 1);
    const float4* A4 = (const float4*)(A + (size_t)rload * K);
    const float4* W4 = (const float4*)W;

    for (int k0 = 0; k0 < K; k0 += KC) {
        __syncthreads();
        // A chunk: each thread owns one row, 8 float4 = 32 k-values, transpose
        float4 v[8];
#pragma unroll
        for (int j = 0; j < 8; j++) v[j] = A4[(k0 >> 2) + j];
#pragma unroll
        for (int j = 0; j < 8; j++) {
            At[4 * j + 0][t] = v[j].x;
            At[4 * j + 1][t] = v[j].y;
            At[4 * j + 2][t] = v[j].z;
            At[4 * j + 3][t] = v[j].w;
        }
        // W chunk: 32x64 floats = 512 float4, 4 per thread
#pragma unroll
        for (int j = 0; j < 4; j++) {
            int idx = t + j * 128;
            int kk = idx >> 4, c4 = idx & 15;
            *((float4*)&Ws[kk][c4 * 4]) = W4[(k0 + kk) * (HID / 4) + c4];
        }
        __syncthreads();
#pragma unroll
        for (int kk = 0; kk < KC; kk++) {
            // B pairs come free as 64-bit loads (adjacent cols)
            unsigned long long bp[4];
            bp[0] = *(const unsigned long long*)&Ws[kk][tc + 0];
            bp[1] = *(const unsigned long long*)&Ws[kk][tc + 2];
            bp[2] = *(const unsigned long long*)&Ws[kk][tc + 4];
            bp[3] = *(const unsigned long long*)&Ws[kk][tc + 6];
            float4 a0 = *(const float4*)&At[kk][tr];
            float4 a1 = *(const float4*)&At[kk][tr + 4];
            float aa[8] = {a0.x, a0.y, a0.z, a0.w, a1.x, a1.y, a1.z, a1.w};
#pragma unroll
            for (int i = 0; i < 8; i++) {
                unsigned long long ad;
                PACK_DUP(ad, aa[i]);
#pragma unroll
                for (int j = 0; j < 4; j++) FMA2(acc[i][j], ad, bp[j]);
            }
        }
    }

#pragma unroll
    for (int i = 0; i < 8; i++) {
        int r = r0 + tr + i;
        if (r < NN) {
            float c0, c1, c2, c3, c4, c5, c6, c7;
            UNPACK2(c0, c1, acc[i][0]);
            UNPACK2(c2, c3, acc[i][1]);
            UNPACK2(c4, c5, acc[i][2]);
            UNPACK2(c6, c7, acc[i][3]);
            float4 o0, o1;
            if (MODE == 0) {
                o0.x = c0 + bias[tc + 0]; o0.y = c1 + bias[tc + 1];
                o0.z = c2 + bias[tc + 2]; o0.w = c3 + bias[tc + 3];
                o1.x = c4 + bias[tc + 4]; o1.y = c5 + bias[tc + 5];
                o1.z = c6 + bias[tc + 6]; o1.w = c7 + bias[tc + 7];
            } else {
                float sc = rsqrtf((float)max(g_dego[r], 1));
                o0.x = c0 * sc; o0.y = c1 * sc; o0.z = c2 * sc; o0.w = c3 * sc;
                o1.x = c4 * sc; o1.y = c5 * sc; o1.z = c6 * sc; o1.w = c7 * sc;
            }
            *((float4*)&C[(size_t)r * HID + tc]) = o0;
            *((float4*)&C[(size_t)r * HID + tc + 4]) = o1;
        }
    }
}

// ---------------- edge scatter: agg[dst] += t[src]  (16 threads / edge, v4 red) ----------------
__global__ void k_scatter(const int* __restrict__ src, const int* __restrict__ dst) {
    int idx = blockIdx.x * blockDim.x + threadIdx.x;
    if (idx >= NE * (HID / 4)) return;
    int e = idx >> 4;
    int c = idx & 15;
    int s = __ldg(&src[e]);
    int d = __ldg(&dst[e]);
    float4 v = ((const float4*)g_t)[s * 16 + c];
    float* p = &g_agg[d * HID + c * 4];
    asm volatile("red.global.add.v4.f32 [%0], {%1,%2,%3,%4};"
                 :: "l"(p), "f"(v.x), "f"(v.y), "f"(v.z), "f"(v.w)
                 : "memory");
}

// ------- combine1: h1 = (h0 + agg*nrmi + b1) * SCALE ; re-zero agg for conv2 -------
__global__ void k_combine1(const float* __restrict__ b1) {
    int idx = blockIdx.x * blockDim.x + threadIdx.x;
    if (idx >= NN * (HID / 4)) return;
    int row = idx >> 4;
    int c4 = idx & 15;
    float4 h = ((const float4*)g_h0)[idx];
    float4 a = ((const float4*)g_agg)[idx];
    float4 b = ((const float4*)b1)[c4];
    float nd = rsqrtf((float)max(g_degi[row], 1));
    float s = d_SCALE;
    float4 r;
    r.x = (h.x + a.x * nd + b.x) * s;
    r.y = (h.y + a.y * nd + b.y) * s;
    r.z = (h.z + a.z * nd + b.z) * s;
    r.w = (h.w + a.w * nd + b.w) * s;
    ((float4*)g_h1)[idx] = r;
    ((float4*)g_agg)[idx] = make_float4(0.f, 0.f, 0.f, 0.f);
}

// ------- combine2 + BN partial sums: h2 -> g_h0, accumulate sum/sumsq (float4) -------
__global__ __launch_bounds__(256) void k_combine2_bn(const float* __restrict__ b2) {
    const int T = gridDim.x * blockDim.x;       // multiple of 16
    int tg = blockIdx.x * blockDim.x + threadIdx.x;
    int c4 = tg & 15;                           // constant per thread
    float4 bb = ((const float4*)b2)[c4];
    float scl = d_SCALE;
    float4 s = make_float4(0.f, 0.f, 0.f, 0.f);
    float4 ss = make_float4(0.f, 0.f, 0.f, 0.f);
    for (int idx = tg; idx < NN * (HID / 4); idx += T) {
        int row = idx >> 4;
        float4 h = ((const float4*)g_h1)[idx];
        float4 a = ((const float4*)g_agg)[idx];
        float nd = rsqrtf((float)max(g_degi[row], 1));
        float4 v;
        v.x = (h.x + a.x * nd + bb.x) * scl;
        v.y = (h.y + a.y * nd + bb.y) * scl;
        v.z = (h.z + a.z * nd + bb.z) * scl;
        v.w = (h.w + a.w * nd + bb.w) * scl;
        ((float4*)g_h0)[idx] = v;
        s.x += v.x; s.y += v.y; s.z += v.z; s.w += v.w;
        ss.x += v.x * v.x; ss.y += v.y * v.y; ss.z += v.z * v.z; ss.w += v.w * v.w;
    }
    __shared__ float4 sh[256];
    sh[threadIdx.x] = s;
    __syncthreads();
    if (threadIdx.x < 16) {
        float4 tot = sh[threadIdx.x];
#pragma unroll
        for (int j = 1; j < 16; j++) {
            float4 o = sh[threadIdx.x + j * 16];
            tot.x += o.x; tot.y += o.y; tot.z += o.z; tot.w += o.w;
        }
        atomicAdd(&g_sum[threadIdx.x * 4 + 0], tot.x);
        atomicAdd(&g_sum[threadIdx.x * 4 + 1], tot.y);
        atomicAdd(&g_sum[threadIdx.x * 4 + 2], tot.z);
        atomicAdd(&g_sum[threadIdx.x * 4 + 3], tot.w);
    }
    __syncthreads();
    sh[threadIdx.x] = ss;
    __syncthreads();
    if (threadIdx.x < 16) {
        float4 tot = sh[threadIdx.x];
#pragma unroll
        for (int j = 1; j < 16; j++) {
            float4 o = sh[threadIdx.x + j * 16];
            tot.x += o.x; tot.y += o.y; tot.z += o.z; tot.w += o.w;
        }
        atomicAdd(&g_ssq[threadIdx.x * 4 + 0], tot.x);
        atomicAdd(&g_ssq[threadIdx.x * 4 + 1], tot.y);
        atomicAdd(&g_ssq[threadIdx.x * 4 + 2], tot.z);
        atomicAdd(&g_ssq[threadIdx.x * 4 + 3], tot.w);
    }
}

__global__ void k_bn_final(const float* __restrict__ gamma, const float* __restrict__ beta) {
    int f = threadIdx.x;
    float mu = g_sum[f] * (1.0f / NN);
    float var = g_ssq[f] * (1.0f / NN) - mu * mu;
    float a = gamma[f] * rsqrtf(var + BN_EPS);
    g_bna[f] = a;
    g_bnc[f] = beta[f] - mu * a;
}

__global__ void k_out(float* __restrict__ out) {
    int idx = blockIdx.x * blockDim.x + threadIdx.x;
    if (idx >= NN * (HID / 4)) return;
    int c4 = idx & 15;
    float4 h = ((const float4*)g_h0)[idx];
    float4 a = ((const float4*)g_bna)[c4];
    float4 c = ((const float4*)g_bnc)[c4];
    float4 r;
    r.x = h.x * a.x + c.x;
    r.y = h.y * a.y + c.y;
    r.z = h.z * a.z + c.z;
    r.w = h.w * a.w + c.w;
    ((float4*)out)[idx] = r;
}

// ---------------- launch ----------------
extern "C" void kernel_launch(void* const* d_in, const int* in_sizes, int n_in,
                              void* d_out, int out_size) {
    const int* src = (const int*)d_in[0];
    const int* dst = (const int*)d_in[1];
    const float* x = (const float*)d_in[2];
    const float* fc_w = (const float*)d_in[3];
    const float* fc_b = (const float*)d_in[4];
    const float* w1 = (const float*)d_in[5];
    const float* b1 = (const float*)d_in[6];
    const float* w2 = (const float*)d_in[7];
    const float* b2 = (const float*)d_in[8];
    const float* gamma = (const float*)d_in[9];
    const float* beta = (const float*)d_in[10];
    float* out = (float*)d_out;

    const int nb_vec = (NN * (HID / 4) + 255) / 256;     // 6250
    const int nb_edge = (NE + 255) / 256;
    const int nb_scat = (NE * (HID / 4) + 255) / 256;    // 50000
    const int nb_gemm = (NN + 127) / 128;                // 782

    k_init<<<(NN + 255) / 256, 256>>>();
    k_degree<<<nb_edge, 256>>>(src, dst);

    // h0 = x @ fc_w + fc_b
    k_gemm<0><<<nb_gemm, 128>>>(x, fc_w, fc_b);

    // conv1
    k_gemm<1><<<nb_gemm, 128>>>(nullptr, w1, nullptr);   // t = (h0@w1)*dego^-1/2
    k_scatter<<<nb_scat, 256>>>(src, dst);
    k_combine1<<<nb_vec, 256>>>(b1);                     // h1 + re-zero agg

    // conv2
    k_gemm<2><<<nb_gemm, 128>>>(nullptr, w2, nullptr);   // t = (h1@w2)*dego^-1/2
    k_scatter<<<nb_scat, 256>>>(src, dst);
    k_combine2_bn<<<256, 256>>>(b2);                     // h2 -> g_h0, BN partials

    k_bn_final<<<1, 64>>>(gamma, beta);
    k_out<<<nb_vec, 256>>>(out);
}